// round 10
// baseline (speedup 1.0000x reference)
#include <cuda_runtime.h>

#define B 32
#define M 32
#define C 1024
#define R 28
#define INV_R2 (1.0f / (R * R))

#define IMGS_PER_BLK 8
#define ROWS_PER_BLK (IMGS_PER_BLK * R)          // 224
#define F4_PER_BLK (ROWS_PER_BLK * R / 4)        // 1568
#define THREADS 224
#define F4_PER_THREAD (F4_PER_BLK / THREADS)     // 7
#define BLKS_PER_B (C / IMGS_PER_BLK)            // 128
#define PROD_BLKS 128                            // 128*224 = 28672 = B*M*R
#define CONS_BLKS (B * C / IMGS_PER_BLK)         // 4096
#define TOTAL_BLKS (PROD_BLKS + CONS_BLKS)       // 4224

// State (allocation-free rule: __device__ globals; zero-initialized at load)
__device__ float g_col[B * M * R];   // column sums of Masks: (B, M, R)
__device__ int   g_cnt  = 0;         // producer-blocks-done counter
__device__ int   g_done = 0;         // all-blocks exit counter (self-reset)

// ---------------------------------------------------------------------------
// Single kernel. Blocks 0..127: mask producers (one thread per col entry,
// __ldcs, MLP=28). Blocks 128..4223: the proven R9 F-core, with col_s
// staging moved BEHIND a wait for the producer flag — the wait sits after
// ~3us of F-load+rowsum work, so the ~1.5us producer phase fully hides.
// Producers are bids 0..127 => guaranteed wave-1 resident (n_conc >= 740)
// and wait on nothing => no deadlock. Counters self-reset via exit counter.
// ---------------------------------------------------------------------------
__global__ void fused_all_kernel(const float* __restrict__ F,
                                 const float* __restrict__ Mk,
                                 float* __restrict__ out) {
    const int tid = threadIdx.x;

    if (blockIdx.x < PROD_BLKS) {
        // ---- Producer: col[b,m,j] = sum_i Masks[b,m,i,j] ----
        int t  = blockIdx.x * THREADS + tid;     // 0..28671, one col entry
        int j  = t % R;
        int bm = t / R;
        const float* p = Mk + (size_t)bm * R * R + j;
        float s = 0.0f;
#pragma unroll
        for (int i = 0; i < R; i++) s += __ldcs(p + i * R);
        g_col[t] = s;
        __threadfence();                          // release col entries
        __syncthreads();                          // whole block's entries out
        if (tid == 0) atomicAdd(&g_cnt, 1);
    } else {
        // ---- Consumer: R9 core ----
        __shared__ float partial[F4_PER_BLK];     // 1568 floats
        __shared__ float rowsum[ROWS_PER_BLK];    // 224 floats
        __shared__ float col_s[M * R];            // 896 floats

        const int blk = blockIdx.x - PROD_BLKS;   // tile id 0..4095
        const int b   = blk / BLKS_PER_B;

        // F load batch: 7 coalesced LDG.128, all in flight (MLP=7).
        const float4* src = reinterpret_cast<const float4*>(F) + (size_t)blk * F4_PER_BLK;
        float4 v[F4_PER_THREAD];
#pragma unroll
        for (int k = 0; k < F4_PER_THREAD; k++) v[k] = src[k * THREADS + tid];

        // f4 horizontal sums -> scalar partials (stride-1 STS).
#pragma unroll
        for (int k = 0; k < F4_PER_THREAD; k++)
            partial[k * THREADS + tid] = (v[k].x + v[k].y) + (v[k].z + v[k].w);
        __syncthreads();

        // Segmented row sum: row t = partial[7t..7t+6] (bank permutation).
        {
            float s = 0.0f;
#pragma unroll
            for (int k = 0; k < F4_PER_THREAD; k++)
                s += partial[tid * F4_PER_THREAD + k];
            rowsum[tid] = s;
        }
        __syncthreads();

        // Wait for producers (normally already done), then stage col[b].
        if (tid == 0) {
            while (atomicAdd(&g_cnt, 0) < PROD_BLKS) __nanosleep(32);
            __threadfence();                      // acquire
        }
        __syncthreads();
        {
            const float* cp = g_col + b * (M * R);
#pragma unroll
            for (int k = 0; k < 4; k++)
                col_s[k * THREADS + tid] = __ldcg(cp + k * THREADS + tid);
        }
        __syncthreads();

        // Einsum tail: 256 outputs = 32 m x 8 c_local.
        const int c0 = (blk % BLKS_PER_B) * IMGS_PER_BLK;
        for (int o = tid; o < M * IMGS_PER_BLK; o += THREADS) {
            int m  = o / IMGS_PER_BLK;
            int cl = o % IMGS_PER_BLK;
            float acc = 0.0f;
#pragma unroll
            for (int r = 0; r < R; r++)
                acc += col_s[m * R + r] * rowsum[cl * R + r];
            out[((size_t)b * M + m) * C + c0 + cl] = acc * INV_R2;
        }
    }

    // ---- Self-reset: last exiting block zeroes the counters ----
    __syncthreads();
    if (tid == 0) {
        int d = atomicAdd(&g_done, 1);
        if (d == TOTAL_BLKS - 1) {
            g_cnt  = 0;
            g_done = 0;
            __threadfence();
        }
    }
}

extern "C" void kernel_launch(void* const* d_in, const int* in_sizes, int n_in,
                              void* d_out, int out_size) {
    const float* F  = (const float*)d_in[0];  // (B, C, R, R)
    const float* Mk = (const float*)d_in[1];  // (B, M, R, R)
    float* out = (float*)d_out;               // (B, M, C)

    fused_all_kernel<<<TOTAL_BLKS, THREADS>>>(F, Mk, out);
}

// round 11
// speedup vs baseline: 1.2510x; 1.2510x over previous
#include <cuda_runtime.h>

#define B 32
#define M 32
#define C 1024
#define R 28
#define INV_R2 (1.0f / (R * R))

#define IMGS_PER_BLK 8
#define ROWS_PER_BLK (IMGS_PER_BLK * R)          // 224
#define F4_PER_BLK (ROWS_PER_BLK * R / 4)        // 1568
#define THREADS 224
#define F4_PER_THREAD (F4_PER_BLK / THREADS)     // 7
#define BLKS_PER_B (C / IMGS_PER_BLK)            // 128

// Scratch (allocation-free rule: __device__ global)
__device__ float g_col[B * M * R];   // column sums of Masks: (B, M, R)

// ---------------------------------------------------------------------------
// Kernel 1 (primary): col[b,m,j] = sum_i Masks[b,m,i,j].
// Triggers programmatic launch completion IMMEDIATELY so the fused kernel's
// grid starts while this one is still loading masks. 28672 threads, __ldcs,
// MLP=28, coalesced across j.
// ---------------------------------------------------------------------------
__global__ void reduce_M_kernel(const float* __restrict__ Mk) {
    cudaTriggerProgrammaticLaunchCompletion();
    int tid = blockIdx.x * blockDim.x + threadIdx.x;
    if (tid >= B * M * R) return;
    int j  = tid % R;
    int bm = tid / R;
    const float* p = Mk + (size_t)bm * R * R + j;
    float s = 0.0f;
#pragma unroll
    for (int i = 0; i < R; i++) s += __ldcs(p + i * R);
    g_col[tid] = s;
}

// ---------------------------------------------------------------------------
// Kernel 2 (secondary, PDL): exact R9 core, but col_s staging is moved
// BEHIND cudaGridDependencySynchronize() — the F-load + partial + rowsum
// phases (~3us of queued DRAM work) execute concurrently with reduce_M
// (~1.5us), and the HW dependency costs no issue slots (unlike R8/R10 spins).
// ---------------------------------------------------------------------------
__global__ void fused_rowsum_einsum_kernel(const float* __restrict__ F,
                                           float* __restrict__ out) {
    __shared__ float partial[F4_PER_BLK];     // 1568 floats = 6.3 KB
    __shared__ float rowsum[ROWS_PER_BLK];    // 224 floats: [c_local*28 + i]
    __shared__ float col_s[M * R];            // 896 floats: [m*28 + r]

    const int tid = threadIdx.x;
    const int blk = blockIdx.x;
    const int b   = blk / BLKS_PER_B;

    // F load batch: 7 coalesced LDG.128, all in flight (MLP=7).
    const float4* src = reinterpret_cast<const float4*>(F) + (size_t)blk * F4_PER_BLK;
    float4 v[F4_PER_THREAD];
#pragma unroll
    for (int k = 0; k < F4_PER_THREAD; k++) v[k] = src[k * THREADS + tid];

    // f4 horizontal sums -> scalar partials (stride-1 STS: conflict-free).
#pragma unroll
    for (int k = 0; k < F4_PER_THREAD; k++)
        partial[k * THREADS + tid] = (v[k].x + v[k].y) + (v[k].z + v[k].w);
    __syncthreads();

    // Segmented row sum: row t = partial[7t..7t+6]; 7 coprime to 32 ->
    // per-phase bank permutation -> conflict-free.
    {
        float s = 0.0f;
#pragma unroll
        for (int k = 0; k < F4_PER_THREAD; k++) s += partial[tid * F4_PER_THREAD + k];
        rowsum[tid] = s;
    }
    __syncthreads();

    // HW wait for reduce_M completion (its results are long since in L2),
    // then stage col[b] (L2-hot: 128 blocks share it).
    cudaGridDependencySynchronize();
    {
        const float* cp = g_col + b * (M * R);
#pragma unroll
        for (int k = 0; k < 4; k++)
            col_s[k * THREADS + tid] = cp[k * THREADS + tid];
    }
    __syncthreads();

    // Einsum tail: 256 outputs = 32 m x 8 c_local.
    const int c0 = (blk % BLKS_PER_B) * IMGS_PER_BLK;
    for (int o = tid; o < M * IMGS_PER_BLK; o += THREADS) {
        int m  = o / IMGS_PER_BLK;
        int cl = o % IMGS_PER_BLK;
        float acc = 0.0f;
#pragma unroll
        for (int r = 0; r < R; r++)
            acc += col_s[m * R + r] * rowsum[cl * R + r];
        out[((size_t)b * M + m) * C + c0 + cl] = acc * INV_R2;
    }
}

extern "C" void kernel_launch(void* const* d_in, const int* in_sizes, int n_in,
                              void* d_out, int out_size) {
    const float* F  = (const float*)d_in[0];  // (B, C, R, R)
    const float* Mk = (const float*)d_in[1];  // (B, M, R, R)
    float* out = (float*)d_out;               // (B, M, C)

    // Primary: plain launch on the capture stream.
    {
        int n = B * M * R;  // 28672
        reduce_M_kernel<<<(n + 255) / 256, 256>>>(Mk);
    }

    // Secondary: PDL launch — may start as soon as the primary triggers.
    {
        cudaLaunchConfig_t cfg = {};
        cfg.gridDim  = dim3((B * C) / IMGS_PER_BLK);   // 4096
        cfg.blockDim = dim3(THREADS);
        cfg.dynamicSmemBytes = 0;
        cfg.stream = 0;
        cudaLaunchAttribute attr[1];
        attr[0].id = cudaLaunchAttributeProgrammaticStreamSerialization;
        attr[0].val.programmaticStreamSerializationAllowed = 1;
        cfg.attrs = attr;
        cfg.numAttrs = 1;
        cudaLaunchKernelEx(&cfg, fused_rowsum_einsum_kernel, F, out);
    }
}